// round 16
// baseline (speedup 1.0000x reference)
#include <cuda_runtime.h>
#include <cuda_fp16.h>
#include <cstdint>

// Conv2d 3x3 s1 p1, NCHW fp32 -> 1D Winograd F(2,3) along w + implicit GEMM
// (mma.sync.m16n8k16.f16, f32 accum). Per output pair (w even/odd):
//   out0 = M0+M1+M2, out1 = M1-M2-M3,  M_xi = sum_{kh,ic} V_xi * U_xi
// V (data transform, fp16, h-padded 114) and U (filter transform, U3 negated)
// precomputed. Conv: CTA = 128 tiles (16h x 8wt) x 64 oc, 4 warps of 64x32,
// 12 chunks (xi,kh) of BK=64(ic), 3-stage cp.async pipeline, register folds.

#define IN_C   64
#define OUT_C  128
#define HWD    112
#define NB     16
#define HW2    (HWD * HWD)
#define BK     64
#define NCHUNK 12
#define LDH    136                     // A halves per k-row (128 tiles + pad)
#define LDB    72                      // B halves per k-row (64 oc + pad)
#define A_HB   (BK * LDH * 2)          // 17408 B
#define B_HB   (BK * LDB * 2)          // 9216 B
#define STAGE_BYTES (A_HB + B_HB)      // 26624
#define NSTAGE 3
#define LDC    260
#define SMEM_BYTES (NSTAGE * STAGE_BYTES)   // 79872 (>= 64*260*4 = 66560 epilogue)

#define VST    (NB * IN_C * 114 * 56)       // halves per xi plane: 6,537,216

__device__ __half g_v[4 * VST];             // [xi][n][ic][h'=114][wt=56]
__device__ __half g_u[12 * IN_C * OUT_C];   // [(xi*3+kh)][ic][oc], xi=3 negated

// ---------------- prep (fused V + U) ----------------
#define V_BLOCKS 3192                 // 16*64*114*7 / 256
#define U_BLOCKS 32                   // 64*128 / 256

__global__ void __launch_bounds__(256)
prep_all(const float* __restrict__ x, const float* __restrict__ w) {
    if (blockIdx.x >= V_BLOCKS) {
        // ---- U = G g (per kh along kw), xi=3 stored negated ----
        const int i  = (blockIdx.x - V_BLOCKS) * 256 + threadIdx.x;  // 0..8191
        const int ic = i >> 7;
        const int oc = i & 127;
        const float* g = w + ((size_t)oc * IN_C + ic) * 9;
#pragma unroll
        for (int kh = 0; kh < 3; kh++) {
            const float g0 = g[kh * 3 + 0];
            const float g1 = g[kh * 3 + 1];
            const float g2 = g[kh * 3 + 2];
            const float u0 = g0;
            const float u1 = 0.5f * (g0 + g1 + g2);
            const float u2 = 0.5f * (g0 - g1 + g2);
            const float u3 = -g2;                     // negated for acc1
            g_u[((0 * 3 + kh) * IN_C + ic) * OUT_C + oc] = __float2half_rn(u0);
            g_u[((1 * 3 + kh) * IN_C + ic) * OUT_C + oc] = __float2half_rn(u1);
            g_u[((2 * 3 + kh) * IN_C + ic) * OUT_C + oc] = __float2half_rn(u2);
            g_u[((3 * 3 + kh) * IN_C + ic) * OUT_C + oc] = __float2half_rn(u3);
        }
        return;
    }
    // ---- V = B^T d along w: 8 wt per thread ----
    const int idx = blockIdx.x * 256 + threadIdx.x;   // (n, ic, hp, wtb)
    const int wtb = idx % 7;
    int r = idx / 7;
    const int hp = r % 114;  r /= 114;
    const int ic = r & 63;
    const int n  = r >> 6;

    uint4 ov[4];
    const int h = hp - 1;
    if ((unsigned)h < HWD) {
        const float* xr = x + (((size_t)(n * IN_C + ic) * HWD) + h) * HWD + wtb * 16;
        float f[18];
        f[0]  = (wtb > 0) ? __ldg(xr - 1) : 0.0f;
#pragma unroll
        for (int q = 0; q < 4; q++) {
            float4 v4 = *reinterpret_cast<const float4*>(xr + q * 4);
            f[1 + q * 4] = v4.x; f[2 + q * 4] = v4.y;
            f[3 + q * 4] = v4.z; f[4 + q * 4] = v4.w;
        }
        f[17] = (wtb < 6) ? __ldg(xr + 16) : 0.0f;

        uint32_t hv[4][8];
#pragma unroll
        for (int j = 0; j < 8; j++) {
            const float d0 = f[2 * j + 0];
            const float d1 = f[2 * j + 1];
            const float d2 = f[2 * j + 2];
            const float d3 = f[2 * j + 3];
            hv[0][j] = __half_as_ushort(__float2half_rn(d0 - d2));
            hv[1][j] = __half_as_ushort(__float2half_rn(d1 + d2));
            hv[2][j] = __half_as_ushort(__float2half_rn(d2 - d1));
            hv[3][j] = __half_as_ushort(__float2half_rn(d1 - d3));
        }
#pragma unroll
        for (int xi = 0; xi < 4; xi++) {
            ov[xi].x = hv[xi][0] | (hv[xi][1] << 16);
            ov[xi].y = hv[xi][2] | (hv[xi][3] << 16);
            ov[xi].z = hv[xi][4] | (hv[xi][5] << 16);
            ov[xi].w = hv[xi][6] | (hv[xi][7] << 16);
        }
    } else {
        ov[0] = ov[1] = ov[2] = ov[3] = make_uint4(0, 0, 0, 0);
    }
#pragma unroll
    for (int xi = 0; xi < 4; xi++) {
        __half* dst = g_v + (size_t)xi * VST
                    + (((size_t)(n * IN_C + ic) * 114) + hp) * 56 + wtb * 8;
        *reinterpret_cast<uint4*>(dst) = ov[xi];
    }
}

// ---------------- main kernel ----------------
__device__ __forceinline__ void mma_f16(float c[4], const uint32_t a[4],
                                        uint32_t b0, uint32_t b1) {
    asm volatile(
        "mma.sync.aligned.m16n8k16.row.col.f32.f16.f16.f32 "
        "{%0,%1,%2,%3}, {%4,%5,%6,%7}, {%8,%9}, {%0,%1,%2,%3};"
        : "+f"(c[0]), "+f"(c[1]), "+f"(c[2]), "+f"(c[3])
        : "r"(a[0]), "r"(a[1]), "r"(a[2]), "r"(a[3]), "r"(b0), "r"(b1));
}

#define LDSM_T(r0, r1, r2, r3, addr)                                          \
    asm volatile("ldmatrix.sync.aligned.m8n8.x4.trans.shared.b16 "            \
                 "{%0,%1,%2,%3}, [%4];"                                       \
                 : "=r"(r0), "=r"(r1), "=r"(r2), "=r"(r3) : "r"(addr))

__global__ void __launch_bounds__(128, 2)
conv_main(const float* __restrict__ bias, float* __restrict__ out)
{
    extern __shared__ __align__(16) char smc[];
    uint32_t sbase;
    asm("{ .reg .u64 t; cvta.to.shared.u64 t, %1; cvt.u32.u64 %0, t; }"
        : "=r"(sbase) : "l"(smc));

    const int tid  = threadIdx.x;
    const int wid  = tid >> 5;
    const int lane = tid & 31;

    // 1568 = 16 n * 7 th * 7 tw * 2 och
    const int b   = blockIdx.x;
    const int och = b & 1;
    int r = b >> 1;
    const int tw = r % 7;  r /= 7;
    const int th = r % 7;
    const int n  = r / 7;
    const int h0  = th * 16;            // output h block (16 rows)
    const int wt0 = tw * 8;             // tile-col block (8 wt -> 16 w)
    const int oc0 = och * 64;

    // ---- A-load bases: 8x 16B per thread, V[xi][n][ic][h0+hh+kh][wt0..+8) ----
    const char* const vbc = reinterpret_cast<const char*>(g_v);
    int baseA[8];                       // halves, without xi/kh offset
    uint32_t dstA[8];
#pragma unroll
    for (int s = 0; s < 8; s++) {
        const int seg = tid + s * 128;  // 0..1023
        const int ic  = seg >> 4;       // 0..63
        const int hh  = seg & 15;       // 0..15
        baseA[s] = ((n * IN_C + ic) * 114 + h0 + hh) * 56 + wt0;
        dstA[s]  = (uint32_t)(ic * LDH + hh * 8) * 2;
    }
    // ---- B-load bases: 4x 16B per thread, U[chunk][ic][oc0..+64) ----
    const char* const ubc = reinterpret_cast<const char*>(g_u);
    int baseB[4];
    uint32_t dstB[4];
#pragma unroll
    for (int s = 0; s < 4; s++) {
        const int seg = tid + s * 128;  // 0..511
        const int kr  = seg >> 3;       // 0..63
        const int ocq = (seg & 7) * 8;
        baseB[s] = kr * OUT_C + oc0 + ocq;
        dstB[s]  = (uint32_t)(kr * LDB + ocq) * 2;
    }

    auto issue = [&](int t, int stage) {
        const uint32_t abase = sbase + stage * STAGE_BYTES;
        const uint32_t bbase = abase + A_HB;
        const int xi = (t < 6) ? ((t < 3) ? 0 : 3) : ((t < 9) ? 1 : 2);
        const int kh = t - ((t < 6) ? ((t < 3) ? 0 : 3) : ((t < 9) ? 6 : 9));
        const long aoff = ((long)xi * VST + (long)kh * 56) * 2;
#pragma unroll
        for (int s = 0; s < 8; s++)
            asm volatile("cp.async.cg.shared.global [%0], [%1], 16;"
                         :: "r"(abase + dstA[s]),
                            "l"(vbc + (long)baseA[s] * 2 + aoff) : "memory");
        const int chunk = xi * 3 + kh;
        const long boff = (long)chunk * (IN_C * OUT_C) * 2;
#pragma unroll
        for (int s = 0; s < 4; s++)
            asm volatile("cp.async.cg.shared.global [%0], [%1], 16;"
                         :: "r"(bbase + dstB[s]),
                            "l"(ubc + (long)baseB[s] * 2 + boff) : "memory");
    };

    // ---- microkernel: 4 warps, warp = 64 tiles x 32 oc ----
    const int wm = wid >> 1;            // tile half (64)
    const int wn = wid & 1;             // oc half (32)
    const uint32_t aoffL = (uint32_t)(((lane >> 4) * 8 + (lane & 7)) * LDH
                                      + wm * 64 + ((lane >> 3) & 1) * 8);
    const uint32_t boffL = (uint32_t)(((((lane >> 3) & 1) * 8) + (lane & 7)) * LDB
                                      + wn * 32 + (lane >> 4) * 8);

    float acc0[4][2][2][4], acc1[4][2][2][4], accT[4][2][2][4];
#pragma unroll
    for (int i = 0; i < 4; i++)
#pragma unroll
        for (int j = 0; j < 2; j++)
#pragma unroll
            for (int h = 0; h < 2; h++)
#pragma unroll
                for (int c = 0; c < 4; c++) {
                    acc0[i][j][h][c] = 0.0f;
                    acc1[i][j][h][c] = 0.0f;
                    accT[i][j][h][c] = 0.0f;
                }

    auto compute = [&](int stage, float (&acc)[4][2][2][4]) {
        const uint32_t abase = sbase + stage * STAGE_BYTES;
        const uint32_t bbase = abase + A_HB;
#pragma unroll
        for (int kk2 = 0; kk2 < 4; kk2++) {
            uint32_t a[4][4];
#pragma unroll
            for (int i = 0; i < 4; i++)
                LDSM_T(a[i][0], a[i][1], a[i][2], a[i][3],
                       abase + (aoffL + kk2 * 16 * LDH + i * 16) * 2);
            uint32_t bfr[2][4];
#pragma unroll
            for (int j2 = 0; j2 < 2; j2++)
                LDSM_T(bfr[j2][0], bfr[j2][1], bfr[j2][2], bfr[j2][3],
                       bbase + (boffL + kk2 * 16 * LDB + j2 * 16) * 2);
#pragma unroll
            for (int j2 = 0; j2 < 2; j2++)
#pragma unroll
                for (int i = 0; i < 4; i++) {
                    mma_f16(acc[i][j2][0], a[i], bfr[j2][0], bfr[j2][1]);
                    mma_f16(acc[i][j2][1], a[i], bfr[j2][2], bfr[j2][3]);
                }
        }
    };

    // ---- pipeline: 12 chunks (xi order 0,3,1,2), 3 stages ----
    issue(0, 0); asm volatile("cp.async.commit_group;" ::: "memory");
    issue(1, 1); asm volatile("cp.async.commit_group;" ::: "memory");

    int cst = 0, ist = 2;
    for (int t = 0; t < NCHUNK; t++) {
        asm volatile("cp.async.wait_group 1;" ::: "memory");
        __syncthreads();
        if (t < 3)       compute(cst, acc0);     // M0
        else if (t < 6)  compute(cst, acc1);     // -M3 (U negated)
        else             compute(cst, accT);     // M1 then M2
        if (t == 8) {                            // accT = M1: out0 += M1, out1 += M1
#pragma unroll
            for (int i = 0; i < 4; i++)
#pragma unroll
                for (int j = 0; j < 2; j++)
#pragma unroll
                    for (int h = 0; h < 2; h++)
#pragma unroll
                        for (int c = 0; c < 4; c++) {
                            acc0[i][j][h][c] += accT[i][j][h][c];
                            acc1[i][j][h][c] += accT[i][j][h][c];
                            accT[i][j][h][c] = 0.0f;
                        }
        }
        if (t == 11) {                           // accT = M2: out0 += M2, out1 -= M2
#pragma unroll
            for (int i = 0; i < 4; i++)
#pragma unroll
                for (int j = 0; j < 2; j++)
#pragma unroll
                    for (int h = 0; h < 2; h++)
#pragma unroll
                        for (int c = 0; c < 4; c++) {
                            acc0[i][j][h][c] += accT[i][j][h][c];
                            acc1[i][j][h][c] -= accT[i][j][h][c];
                        }
        }
        if (++cst == NSTAGE) cst = 0;
        if (t + 2 < NCHUNK) {
            issue(t + 2, ist);
            if (++ist == NSTAGE) ist = 0;
        }
        asm volatile("cp.async.commit_group;" ::: "memory");
    }

    // ---- epilogue: interleave acc0 (even w) / acc1 (odd w) in SMEM, coalesced out ----
    __syncthreads();
    float* const Cs = reinterpret_cast<float*>(smc);
    const int g  = lane >> 2;
    const int t4 = lane & 3;

#pragma unroll
    for (int i = 0; i < 4; i++)
#pragma unroll
        for (int j2 = 0; j2 < 2; j2++)
#pragma unroll
            for (int nh = 0; nh < 2; nh++) {
                const int occ = wn * 32 + j2 * 16 + nh * 8 + 2 * t4;
#pragma unroll
                for (int ch = 0; ch < 2; ch++) {       // c pair: rows g, g+8
                    const int m  = wm * 64 + i * 16 + ch * 8 + g;
                    const int hh = m >> 3;
                    const int px = hh * 16 + (m & 7) * 2;
                    Cs[occ * LDC + px]           = acc0[i][j2][nh][2 * ch];
                    Cs[occ * LDC + px + 1]       = acc1[i][j2][nh][2 * ch];
                    Cs[(occ + 1) * LDC + px]     = acc0[i][j2][nh][2 * ch + 1];
                    Cs[(occ + 1) * LDC + px + 1] = acc1[i][j2][nh][2 * ch + 1];
                }
            }
    __syncthreads();

    // 64 oc x (16h x 16w) = 4096 float4 -> 128 threads x 32 iters
    float* const ob = out + (size_t)n * OUT_C * HW2 + h0 * HWD + tw * 16;
#pragma unroll
    for (int r2 = 0; r2 < 32; r2++) {
        const int f   = tid + 128 * r2;     // (oc, hh, w4)
        const int w4  = f & 3;
        const int hh  = (f >> 2) & 15;
        const int oc  = f >> 6;
        float4 v = *reinterpret_cast<const float4*>(&Cs[oc * LDC + hh * 16 + w4 * 4]);
        const float bv = __ldg(bias + oc0 + oc);
        v.x += bv; v.y += bv; v.z += bv; v.w += bv;
        *reinterpret_cast<float4*>(ob + (size_t)(oc0 + oc) * HW2 + hh * HWD + w4 * 4) = v;
    }
}

extern "C" void kernel_launch(void* const* d_in, const int* in_sizes, int n_in,
                              void* d_out, int out_size)
{
    const float* x    = (const float*)d_in[0];
    const float* w    = (const float*)d_in[1];
    const float* bias = (const float*)d_in[2];
    float* out        = (float*)d_out;

    prep_all<<<V_BLOCKS + U_BLOCKS, 256>>>(x, w);

    cudaFuncSetAttribute(conv_main,
                         cudaFuncAttributeMaxDynamicSharedMemorySize, SMEM_BYTES);
    conv_main<<<NB * 7 * 7 * 2, 128, SMEM_BYTES>>>(bias, out);
}